// round 5
// baseline (speedup 1.0000x reference)
#include <cuda_runtime.h>
#include <cuda_bf16.h>
#include <cstdint>

#define N_NODES 100000
#define N_EDGES 3200000
#define F_IN 128
#define F_HID 16
#define F_OUT 32

// ---------------- scratch (device globals; no allocation allowed) ----------
__device__ int   d_cnt[N_NODES];           // in-degree (targets, no self-loop)
__device__ int   d_fill[N_NODES];          // CSR fill cursors
__device__ int   d_off[N_NODES + 1];       // CSR offsets
__device__ int   d_src[N_EDGES];           // CSR: sources grouped by target
__device__ float d_dinv[N_NODES];
__device__ float d_g1[N_NODES * F_HID];    // dinv[i] * (x W1)[i]
__device__ float d_g2[N_NODES * F_OUT];    // dinv[i] * (h W2)[i]

// ---------------- kernel: zero counters ------------------------------------
__global__ void k_zero(int n) {
    int i = blockIdx.x * blockDim.x + threadIdx.x;
    if (i < n) { d_cnt[i] = 0; d_fill[i] = 0; }
}

// ---------------- kernel: in-degree count (edge_index stored as int32) -----
__global__ void k_count(const int* __restrict__ ei, int E) {
    int e = blockIdx.x * blockDim.x + threadIdx.x;
    if (e >= E) return;
    int c = ei[E + e];                     // edge_index[1][e] (target)
    atomicAdd(&d_cnt[c], 1);
}

// ---------------- kernel: offsets (single block, shuffle-only scan) --------
__global__ void k_offsets(int N) {
    __shared__ int warpsum[32];
    __shared__ int warpexcl[32];
    int t = threadIdx.x;
    int lane = t & 31, w = t >> 5;
    const int CH = (N + 1023) >> 10;       // 98

    int lo = t * CH;
    int hi = lo + CH; if (hi > N) hi = N;
    if (lo > N) lo = N;

    int local = 0;
    for (int i = lo; i < hi; i++) local += d_cnt[i];

    // warp-inclusive scan (registers only)
    int x = local;
    #pragma unroll
    for (int o = 1; o < 32; o <<= 1) {
        int v = __shfl_up_sync(0xFFFFFFFFu, x, o);
        if (lane >= o) x += v;
    }
    if (lane == 31) warpsum[w] = x;
    __syncthreads();
    if (w == 0) {
        int orig = warpsum[lane];
        int y = orig;
        #pragma unroll
        for (int o = 1; o < 32; o <<= 1) {
            int v = __shfl_up_sync(0xFFFFFFFFu, y, o);
            if (lane >= o) y += v;
        }
        warpexcl[lane] = y - orig;         // exclusive base, safe index
    }
    __syncthreads();

    int run = (x - local) + warpexcl[w];   // exclusive prefix for this chunk
    for (int i = lo; i < hi; i++) {
        int c = d_cnt[i];
        d_off[i] = run;
        run += c;
        d_dinv[i] = rsqrtf((float)c + 1.0f);   // +1 = self loop
    }
    if (t == 1023) d_off[N] = run;         // == E
}

// ---------------- CSR fill --------------------------------------------------
__global__ void k_fill(const int* __restrict__ ei, int E) {
    int e = blockIdx.x * blockDim.x + threadIdx.x;
    if (e >= E) return;
    int r = ei[e];                         // source
    int c = ei[E + e];                     // target
    int p = d_off[c] + atomicAdd(&d_fill[c], 1);
    d_src[p] = r;
}

// ---------------- GEMM1: g1 = dinv * (x @ W1) -------------------------------
// block = 256 threads, 32 rows/block; 100000 = 32 * 3125.
__global__ void k_gemm1(const float* __restrict__ x, const float* __restrict__ W1) {
    __shared__ float xs[32 * 129];
    __shared__ float ws[F_IN * F_HID];
    int tid = threadIdx.x;
    int row0 = blockIdx.x * 32;

    for (int i = tid; i < F_IN * F_HID; i += 256) ws[i] = W1[i];
    for (int i = tid; i < 32 * F_IN; i += 256) {
        int r = i >> 7, k = i & 127;
        xs[r * 129 + k] = x[(row0 + r) * F_IN + k];
    }
    __syncthreads();

    #pragma unroll
    for (int it = 0; it < 2; it++) {
        int id = tid + it * 256;            // 512 items: 32 rows x 16 outs
        int r = id >> 4, j = id & 15;
        float acc = 0.f;
        #pragma unroll
        for (int k = 0; k < F_IN; k++)
            acc += xs[r * 129 + k] * ws[k * F_HID + j];
        int node = row0 + r;
        d_g1[node * F_HID + j] = acc * d_dinv[node];
    }
}

// ---------------- layer1 aggregate + ReLU + GEMM2 (warp per node) ----------
__global__ void k_agg1(const float* __restrict__ W2, const float* __restrict__ b1) {
    __shared__ float ws[F_HID * F_OUT];
    __shared__ float bs[F_HID];
    int tid = threadIdx.x;
    for (int i = tid; i < F_HID * F_OUT; i += 256) ws[i] = W2[i];
    if (tid < F_HID) bs[tid] = b1[tid];
    __syncthreads();

    int node = (blockIdx.x * 256 + tid) >> 5;     // exactly N_NODES warps
    int lane = tid & 31;
    int f = lane & 15;
    int half = lane >> 4;
    int s = d_off[node], e = d_off[node + 1];

    float a0 = 0.f, a1 = 0.f, a2 = 0.f, a3 = 0.f;
    int i = s + half;                              // halves interleave edges
    for (; i + 6 < e; i += 8) {                    // 4 independent gathers
        int s0 = d_src[i],     s1 = d_src[i + 2];
        int s2 = d_src[i + 4], s3 = d_src[i + 6];
        a0 += d_g1[s0 * F_HID + f];
        a1 += d_g1[s1 * F_HID + f];
        a2 += d_g1[s2 * F_HID + f];
        a3 += d_g1[s3 * F_HID + f];
    }
    for (; i < e; i += 2) a0 += d_g1[d_src[i] * F_HID + f];

    float acc = (a0 + a1) + (a2 + a3);
    acc += __shfl_xor_sync(0xFFFFFFFFu, acc, 16);  // combine halves

    float dv = d_dinv[node];
    float h = fmaxf((acc + d_g1[node * F_HID + f]) * dv + bs[f], 0.f);

    // GEMM2 across the warp: lane j computes output feature j
    float o2 = 0.f;
    #pragma unroll
    for (int k = 0; k < F_HID; k++) {
        float hk = __shfl_sync(0xFFFFFFFFu, h, k);
        o2 += hk * ws[k * F_OUT + lane];
    }
    d_g2[node * F_OUT + lane] = o2 * dv;
}

// ---------------- layer2 aggregate + bias + log_softmax (warp per node) ----
__global__ void k_agg2(const float* __restrict__ b2, float* __restrict__ out) {
    int tid = threadIdx.x;
    int node = (blockIdx.x * 256 + tid) >> 5;
    int lane = tid & 31;
    int s = d_off[node], e = d_off[node + 1];

    float a0 = 0.f, a1 = 0.f, a2 = 0.f, a3 = 0.f;
    int i = s;
    for (; i + 3 < e; i += 4) {                    // 4 independent gathers
        int s0 = d_src[i],     s1 = d_src[i + 1];
        int s2 = d_src[i + 2], s3 = d_src[i + 3];
        a0 += d_g2[s0 * F_OUT + lane];
        a1 += d_g2[s1 * F_OUT + lane];
        a2 += d_g2[s2 * F_OUT + lane];
        a3 += d_g2[s3 * F_OUT + lane];
    }
    for (; i < e; i++) a0 += d_g2[d_src[i] * F_OUT + lane];

    float v = ((a0 + a1) + (a2 + a3) + d_g2[node * F_OUT + lane]) * d_dinv[node]
              + b2[lane];

    float m = v;
    #pragma unroll
    for (int o = 16; o; o >>= 1) m = fmaxf(m, __shfl_xor_sync(0xFFFFFFFFu, m, o));
    float ex = expf(v - m);
    float sum = ex;
    #pragma unroll
    for (int o = 16; o; o >>= 1) sum += __shfl_xor_sync(0xFFFFFFFFu, sum, o);
    out[node * F_OUT + lane] = v - m - logf(sum);
}

// ---------------- launcher --------------------------------------------------
extern "C" void kernel_launch(void* const* d_in, const int* in_sizes, int n_in,
                              void* d_out, int out_size) {
    const float* x  = (const float*)d_in[0];       // [N, 128] f32
    const int*   ei = (const int*)d_in[1];         // [2, E] int32 (harness downcasts int64)
    const float* W1 = (const float*)d_in[2];       // [128, 16]
    const float* b1 = (const float*)d_in[3];       // [16]
    const float* W2 = (const float*)d_in[4];       // [16, 32]
    const float* b2 = (const float*)d_in[5];       // [32]
    float* out = (float*)d_out;

    int N = in_sizes[0] / F_IN;     // 100000
    int E = in_sizes[1] / 2;        // 3200000

    k_zero   <<<(N + 255) / 256, 256>>>(N);
    k_count  <<<(E + 255) / 256, 256>>>(ei, E);
    k_offsets<<<1, 1024>>>(N);
    k_fill   <<<(E + 255) / 256, 256>>>(ei, E);
    k_gemm1  <<<N / 32, 256>>>(x, W1);
    k_agg1   <<<(N * 32) / 256, 256>>>(W2, b1);    // 1 warp per node
    k_agg2   <<<(N * 32) / 256, 256>>>(b2, out);
}

// round 7
// speedup vs baseline: 1.4169x; 1.4169x over previous
#include <cuda_runtime.h>
#include <cuda_bf16.h>
#include <cstdint>

#define N_NODES 100000
#define N_EDGES 3200000
#define F_IN 128
#define F_HID 16
#define F_OUT 32
#define SCAN_B 1024
#define NB_SCAN ((N_NODES + SCAN_B - 1) / SCAN_B)   // 98

// ---------------- scratch (device globals; no allocation allowed) ----------
__device__ int   d_cnt[N_NODES];           // in-degree (targets, no self-loop)
__device__ int   d_fill[N_NODES];          // CSR fill cursors
__device__ int   d_off[N_NODES + 1];       // CSR offsets
__device__ int   d_bsum[NB_SCAN];          // per-block sums -> exclusive bases
__device__ int   d_src[N_EDGES];           // CSR: sources grouped by target
__device__ float d_dinv[N_NODES];
__device__ float d_g1[N_NODES * F_HID];    // dinv[i] * (x W1)[i]
__device__ float d_g2[N_NODES * F_OUT];    // dinv[i] * (h W2)[i]

// ---------------- kernel: zero counts ---------------------------------------
__global__ void k_zero(int n) {
    int i = blockIdx.x * blockDim.x + threadIdx.x;
    if (i < n) d_cnt[i] = 0;
}

// ---------------- kernel: in-degree count ----------------------------------
__global__ void k_count(const int* __restrict__ ei, int E) {
    int e = blockIdx.x * blockDim.x + threadIdx.x;
    if (e >= E) return;
    atomicAdd(&d_cnt[ei[E + e]], 1);       // edge_index[1][e] (target)
}

// ---------------- scan A: per-block sums (98 blocks x 1024) -----------------
__global__ void k_blocksum(int N) {
    __shared__ int ws[32];
    int t = threadIdx.x, lane = t & 31, w = t >> 5;
    int i = blockIdx.x * SCAN_B + t;
    int s = (i < N) ? d_cnt[i] : 0;
    #pragma unroll
    for (int o = 16; o; o >>= 1) s += __shfl_xor_sync(0xFFFFFFFFu, s, o);
    if (lane == 0) ws[w] = s;
    __syncthreads();
    if (t < 32) {
        int v = ws[t];
        #pragma unroll
        for (int o = 16; o; o >>= 1) v += __shfl_xor_sync(0xFFFFFFFFu, v, o);
        if (t == 0) d_bsum[blockIdx.x] = v;
    }
}

// ---------------- scan B: exclusive scan of 98 block sums (1 warp) ----------
__global__ void k_scanb(int nb, int N) {
    int lane = threadIdx.x;
    int carry = 0;
    for (int base = 0; base < nb; base += 32) {
        int idx = base + lane;
        int v = (idx < nb) ? d_bsum[idx] : 0;
        int x = v;
        #pragma unroll
        for (int o = 1; o < 32; o <<= 1) {
            int u = __shfl_up_sync(0xFFFFFFFFu, x, o);
            if (lane >= o) x += u;
        }
        if (idx < nb) d_bsum[idx] = carry + x - v;   // exclusive
        carry += __shfl_sync(0xFFFFFFFFu, x, 31);    // chunk total
    }
    if (lane == 0) d_off[N] = carry;                 // == E
}

// ---------------- scan C: write offsets + dinv + zero fill ------------------
__global__ void k_writeoff(int N) {
    __shared__ int warpsum[32];
    __shared__ int warpexcl[32];
    int t = threadIdx.x, lane = t & 31, w = t >> 5;
    int i = blockIdx.x * SCAN_B + t;
    int c = (i < N) ? d_cnt[i] : 0;
    int x = c;
    #pragma unroll
    for (int o = 1; o < 32; o <<= 1) {
        int u = __shfl_up_sync(0xFFFFFFFFu, x, o);
        if (lane >= o) x += u;
    }
    if (lane == 31) warpsum[w] = x;
    __syncthreads();
    if (t < 32) {
        int orig = warpsum[t];
        int y = orig;
        #pragma unroll
        for (int o = 1; o < 32; o <<= 1) {
            int u = __shfl_up_sync(0xFFFFFFFFu, y, o);
            if (t >= o) y += u;
        }
        warpexcl[t] = y - orig;                      // exclusive, safe index
    }
    __syncthreads();
    if (i < N) {
        int pre = (x - c) + warpexcl[w] + d_bsum[blockIdx.x];
        d_off[i]  = pre;
        d_fill[i] = 0;
        d_dinv[i] = rsqrtf((float)c + 1.0f);         // +1 = self loop
    }
}

// ---------------- CSR fill --------------------------------------------------
__global__ void k_fill(const int* __restrict__ ei, int E) {
    int e = blockIdx.x * blockDim.x + threadIdx.x;
    if (e >= E) return;
    int r = ei[e];                         // source
    int c = ei[E + e];                     // target
    int p = d_off[c] + atomicAdd(&d_fill[c], 1);
    d_src[p] = r;
}

// ---------------- GEMM1: g1 = dinv * (x @ W1) -------------------------------
// block = 256 threads, 32 rows/block; 100000 = 32 * 3125.
__global__ void k_gemm1(const float* __restrict__ x, const float* __restrict__ W1) {
    __shared__ float xs[32 * 129];
    __shared__ float ws[F_IN * F_HID];
    int tid = threadIdx.x;
    int row0 = blockIdx.x * 32;

    for (int i = tid; i < F_IN * F_HID; i += 256) ws[i] = W1[i];
    for (int i = tid; i < 32 * F_IN; i += 256) {
        int r = i >> 7, k = i & 127;
        xs[r * 129 + k] = x[(row0 + r) * F_IN + k];
    }
    __syncthreads();

    #pragma unroll
    for (int it = 0; it < 2; it++) {
        int id = tid + it * 256;            // 512 items: 32 rows x 16 outs
        int r = id >> 4, j = id & 15;
        float acc = 0.f;
        #pragma unroll
        for (int k = 0; k < F_IN; k++)
            acc += xs[r * 129 + k] * ws[k * F_HID + j];
        int node = row0 + r;
        d_g1[node * F_HID + j] = acc * d_dinv[node];
    }
}

// ---------------- layer1 aggregate + ReLU + GEMM2 (warp per node) ----------
__global__ void k_agg1(const float* __restrict__ W2, const float* __restrict__ b1) {
    __shared__ float ws[F_HID * F_OUT];
    __shared__ float bs[F_HID];
    int tid = threadIdx.x;
    for (int i = tid; i < F_HID * F_OUT; i += 256) ws[i] = W2[i];
    if (tid < F_HID) bs[tid] = b1[tid];
    __syncthreads();

    int node = (blockIdx.x * 256 + tid) >> 5;     // exactly N_NODES warps
    int lane = tid & 31;
    int f = lane & 15;
    int half = lane >> 4;
    int s = d_off[node], e = d_off[node + 1];

    float a0 = 0.f, a1 = 0.f, a2 = 0.f, a3 = 0.f;
    float a4 = 0.f, a5 = 0.f, a6 = 0.f, a7 = 0.f;
    int i = s + half;                              // halves interleave edges
    for (; i + 14 < e; i += 16) {                  // 8 independent gathers
        int s0 = d_src[i],      s1 = d_src[i + 2];
        int s2 = d_src[i + 4],  s3 = d_src[i + 6];
        int s4 = d_src[i + 8],  s5 = d_src[i + 10];
        int s6 = d_src[i + 12], s7 = d_src[i + 14];
        a0 += d_g1[s0 * F_HID + f];
        a1 += d_g1[s1 * F_HID + f];
        a2 += d_g1[s2 * F_HID + f];
        a3 += d_g1[s3 * F_HID + f];
        a4 += d_g1[s4 * F_HID + f];
        a5 += d_g1[s5 * F_HID + f];
        a6 += d_g1[s6 * F_HID + f];
        a7 += d_g1[s7 * F_HID + f];
    }
    for (; i + 6 < e; i += 8) {
        int s0 = d_src[i],     s1 = d_src[i + 2];
        int s2 = d_src[i + 4], s3 = d_src[i + 6];
        a0 += d_g1[s0 * F_HID + f];
        a1 += d_g1[s1 * F_HID + f];
        a2 += d_g1[s2 * F_HID + f];
        a3 += d_g1[s3 * F_HID + f];
    }
    for (; i < e; i += 2) a0 += d_g1[d_src[i] * F_HID + f];

    float acc = ((a0 + a1) + (a2 + a3)) + ((a4 + a5) + (a6 + a7));
    acc += __shfl_xor_sync(0xFFFFFFFFu, acc, 16);  // combine halves

    float dv = d_dinv[node];
    float h = fmaxf((acc + d_g1[node * F_HID + f]) * dv + bs[f], 0.f);

    // GEMM2 across the warp: lane j computes output feature j
    float o2 = 0.f;
    #pragma unroll
    for (int k = 0; k < F_HID; k++) {
        float hk = __shfl_sync(0xFFFFFFFFu, h, k);
        o2 += hk * ws[k * F_OUT + lane];
    }
    d_g2[node * F_OUT + lane] = o2 * dv;
}

// ---------------- layer2 aggregate + bias + log_softmax (warp per node) ----
__global__ void k_agg2(const float* __restrict__ b2, float* __restrict__ out) {
    int tid = threadIdx.x;
    int node = (blockIdx.x * 256 + tid) >> 5;
    int lane = tid & 31;
    int s = d_off[node], e = d_off[node + 1];

    float a0 = 0.f, a1 = 0.f, a2 = 0.f, a3 = 0.f;
    float a4 = 0.f, a5 = 0.f, a6 = 0.f, a7 = 0.f;
    int i = s;
    for (; i + 7 < e; i += 8) {                    // 8 independent gathers
        int s0 = d_src[i],     s1 = d_src[i + 1];
        int s2 = d_src[i + 2], s3 = d_src[i + 3];
        int s4 = d_src[i + 4], s5 = d_src[i + 5];
        int s6 = d_src[i + 6], s7 = d_src[i + 7];
        a0 += d_g2[s0 * F_OUT + lane];
        a1 += d_g2[s1 * F_OUT + lane];
        a2 += d_g2[s2 * F_OUT + lane];
        a3 += d_g2[s3 * F_OUT + lane];
        a4 += d_g2[s4 * F_OUT + lane];
        a5 += d_g2[s5 * F_OUT + lane];
        a6 += d_g2[s6 * F_OUT + lane];
        a7 += d_g2[s7 * F_OUT + lane];
    }
    for (; i < e; i++) a0 += d_g2[d_src[i] * F_OUT + lane];

    float v = (((a0 + a1) + (a2 + a3)) + ((a4 + a5) + (a6 + a7))
               + d_g2[node * F_OUT + lane]) * d_dinv[node] + b2[lane];

    float m = v;
    #pragma unroll
    for (int o = 16; o; o >>= 1) m = fmaxf(m, __shfl_xor_sync(0xFFFFFFFFu, m, o));
    float ex = expf(v - m);
    float sum = ex;
    #pragma unroll
    for (int o = 16; o; o >>= 1) sum += __shfl_xor_sync(0xFFFFFFFFu, sum, o);
    out[node * F_OUT + lane] = v - m - logf(sum);
}

// ---------------- launcher --------------------------------------------------
extern "C" void kernel_launch(void* const* d_in, const int* in_sizes, int n_in,
                              void* d_out, int out_size) {
    const float* x  = (const float*)d_in[0];       // [N, 128] f32
    const int*   ei = (const int*)d_in[1];         // [2, E] int32
    const float* W1 = (const float*)d_in[2];       // [128, 16]
    const float* b1 = (const float*)d_in[3];       // [16]
    const float* W2 = (const float*)d_in[4];       // [16, 32]
    const float* b2 = (const float*)d_in[5];       // [32]
    float* out = (float*)d_out;

    int N = in_sizes[0] / F_IN;     // 100000
    int E = in_sizes[1] / 2;        // 3200000
    int nb = (N + SCAN_B - 1) / SCAN_B;            // 98

    k_zero    <<<(N + 255) / 256, 256>>>(N);
    k_count   <<<(E + 255) / 256, 256>>>(ei, E);
    k_blocksum<<<nb, SCAN_B>>>(N);
    k_scanb   <<<1, 32>>>(nb, N);
    k_writeoff<<<nb, SCAN_B>>>(N);
    k_fill    <<<(E + 255) / 256, 256>>>(ei, E);
    k_gemm1   <<<N / 32, 256>>>(x, W1);
    k_agg1    <<<(N * 32) / 256, 256>>>(W2, b1);   // 1 warp per node
    k_agg2    <<<(N * 32) / 256, 256>>>(b2, out);
}